// round 1
// baseline (speedup 1.0000x reference)
#include <cuda_runtime.h>
#include <cuda_bf16.h>

// BiLinearInteractionLayer: out[b, p, :] = (x[b,i_p,:] @ W) * x[b,j_p,:]
// x: [2048, 40, 64] fp32, W: [64, 64] fp32, out: [2048, 780*64] fp32.
// One CTA per batch row. Phase 1: stage x row-block + W in smem.
// Phase 2: xw = x @ W with float4-tiled register GEMM (W column reuse).
// Phase 3: stream 780*16 float4 products to gmem, coalesced.

#define F_NUM   40
#define F_PAD   48          // padded rows so the GEMM tile loop needs no guard on reads
#define EDIM    64
#define NPAIR   780         // F*(F-1)/2
#define TPB     256
#define BATCH_N 2048

__global__ __launch_bounds__(TPB, 1)
void bilinear_interact_kernel(const float* __restrict__ x,
                              const float* __restrict__ w,
                              float* __restrict__ out)
{
    __shared__ float sx [F_PAD * EDIM];   // 12 KB (rows 40..47 uninitialized, never stored)
    __shared__ float sxw[F_NUM * EDIM];   // 10 KB
    __shared__ float sw [EDIM * EDIM];    // 16 KB
    __shared__ unsigned char spi[NPAIR];
    __shared__ unsigned char spj[NPAIR];

    const int b   = blockIdx.x;
    const int tid = threadIdx.x;

    // ---- Phase 1: stage inputs ------------------------------------------
    {
        const float4* xg  = reinterpret_cast<const float4*>(x + (size_t)b * F_NUM * EDIM);
        float4*       sx4 = reinterpret_cast<float4*>(sx);
        #pragma unroll
        for (int t = tid; t < F_NUM * EDIM / 4; t += TPB) sx4[t] = xg[t];

        const float4* wg  = reinterpret_cast<const float4*>(w);
        float4*       sw4 = reinterpret_cast<float4*>(sw);
        #pragma unroll
        for (int t = tid; t < EDIM * EDIM / 4; t += TPB) sw4[t] = wg[t];
    }

    // pair LUT: combinations(range(40), 2) order
    if (tid < F_NUM - 1) {
        const int i    = tid;
        const int base = i * (F_NUM - 1) - (i * (i - 1)) / 2;
        for (int j = i + 1; j < F_NUM; j++) {
            spi[base + j - i - 1] = (unsigned char)i;
            spj[base + j - i - 1] = (unsigned char)j;
        }
    }
    __syncthreads();

    // ---- Phase 2: xw = x @ W  (40x64 @ 64x64) ---------------------------
    // Thread owns one float4 column of W (col = tid&15) and 3 x-rows
    // (fbase, fbase+16, fbase+32). One LDS.128 of W per k, reused 3x.
    {
        const int col   = tid & 15;    // float4 column index (d/4)
        const int fbase = tid >> 4;    // 0..15
        const float4* swv  = reinterpret_cast<const float4*>(sw);
        float4*       sxw4 = reinterpret_cast<float4*>(sxw);

        float4 acc0 = make_float4(0.f, 0.f, 0.f, 0.f);
        float4 acc1 = acc0;
        float4 acc2 = acc0;

        #pragma unroll
        for (int k = 0; k < EDIM; k++) {
            const float4 wv = swv[k * 16 + col];
            const float a0 = sx[ fbase       * EDIM + k];
            const float a1 = sx[(fbase + 16) * EDIM + k];
            const float a2 = sx[(fbase + 32) * EDIM + k];  // padded-row read if fbase>=8
            acc0.x += a0 * wv.x; acc0.y += a0 * wv.y; acc0.z += a0 * wv.z; acc0.w += a0 * wv.w;
            acc1.x += a1 * wv.x; acc1.y += a1 * wv.y; acc1.z += a1 * wv.z; acc1.w += a1 * wv.w;
            acc2.x += a2 * wv.x; acc2.y += a2 * wv.y; acc2.z += a2 * wv.z; acc2.w += a2 * wv.w;
        }

        sxw4[ fbase       * 16 + col] = acc0;
        sxw4[(fbase + 16) * 16 + col] = acc1;
        if (fbase < 8)
            sxw4[(fbase + 32) * 16 + col] = acc2;
    }
    __syncthreads();

    // ---- Phase 3: stream pair products ----------------------------------
    // out[b, p, d] = sxw[i_p, d] * sx[j_p, d]; 12480 float4 per batch row.
    {
        float4*       out4 = reinterpret_cast<float4*>(out + (size_t)b * NPAIR * EDIM);
        const float4* sxc4 = reinterpret_cast<const float4*>(sx);
        const float4* sxw4 = reinterpret_cast<const float4*>(sxw);

        #pragma unroll 4
        for (int t = tid; t < NPAIR * EDIM / 4; t += TPB) {
            const int p  = t >> 4;     // pair index
            const int d4 = t & 15;     // float4 lane within the pair
            const int i  = spi[p];
            const int j  = spj[p];
            const float4 a = sxw4[i * 16 + d4];
            const float4 v = sxc4[j * 16 + d4];
            out4[t] = make_float4(a.x * v.x, a.y * v.y, a.z * v.z, a.w * v.w);
        }
    }
}

extern "C" void kernel_launch(void* const* d_in, const int* in_sizes, int n_in,
                              void* d_out, int out_size)
{
    const float* x = (const float*)d_in[0];   // [2048, 40, 64]
    const float* w = (const float*)d_in[1];   // [64, 64]
    float* out = (float*)d_out;               // [2048, 780*64]
    (void)in_sizes; (void)n_in; (void)out_size;

    bilinear_interact_kernel<<<BATCH_N, TPB>>>(x, w, out);
}